// round 10
// baseline (speedup 1.0000x reference)
#include <cuda_runtime.h>
#include <cstdint>

// RandomRoll: out[b,c,h,w] = x[b,c,(h - sh) & 511, (w - sw) & 511]
// x: [64, 3, 512, 512] fp32; shifts: [64, 2] int32.
// R9: persistent grid-stride kernel (148 SMs x 8 CTAs, zero wave transitions).
// One 512-float row per warp-iteration; whole source row loaded with 4 aligned
// LDG.128 (rotated window), circular realign closes in-warp via shuffle.

static constexpr int HMASK = 511;
static constexpr int WMASK = 511;
static constexpr int TPB   = 256;
static constexpr int NSM   = 148;
static constexpr int BLK_PER_SM = 8;      // 256 thr * 8 = 2048 thr/SM @ ~32 regs
static constexpr unsigned FULL = 0xffffffffu;

// Realign output vec (lane + 32K) from the in-register source row A[0..3].
// off warp-uniform (0..3). Neighbor of A[K]@lane is A[K]@lane+1; lane 31's
// neighbor is A[(K+1)&3]@lane0, contributed by lane 0 into the shuffle.
template<int K>
__device__ __forceinline__ float4 realign(const float4 A[4], int off, int lane)
{
    float4 a = A[K];
    if (off == 0) return a;
    const float4 an = A[(K + 1) & 3];
    int src = (lane + 1) & 31;
    float4 B;
    B.x = __shfl_sync(FULL, (lane == 0) ? an.x : a.x, src);
    B.y = __shfl_sync(FULL, (lane == 0) ? an.y : a.y, src);
    B.z = __shfl_sync(FULL, (lane == 0) ? an.z : a.z, src);
    B.w = __shfl_sync(FULL, (lane == 0) ? an.w : a.w, src);
    if (off == 1) return make_float4(a.y, a.z, a.w, B.x);
    if (off == 2) return make_float4(a.z, a.w, B.x, B.y);
    return make_float4(a.w, B.x, B.y, B.z);
}

__global__ void __launch_bounds__(TPB, BLK_PER_SM)
random_roll_rows(const float4* __restrict__ x4,
                 const int*    __restrict__ shifts,
                 float4*       __restrict__ out4,
                 int n_rows)   // rows = (b*3+c)*512 + h; 128 float4 each
{
    int lane    = threadIdx.x & 31;
    int warp    = blockIdx.x * (TPB / 32) + (threadIdx.x >> 5);
    int n_warps = gridDim.x * (TPB / 32);

    for (int row = warp; row < n_rows; row += n_warps) {
        int h  = row & HMASK;
        int bc = row >> 9;
        int b  = bc / 3;

        int sh = __ldg(&shifts[2 * b]);
        int sw = __ldg(&shifts[2 * b + 1]);

        const float4* src = x4 + ((size_t)((bc << 9) | ((h - sh) & HMASK)) << 7);
        int s0  = (-sw) & WMASK;    // first source float of the rolled row
        int off = s0 & 3;           // intra-vec misalignment, warp-uniform
        int v0  = s0 >> 2;

        // 4 aligned LDG.128 back-to-back: entire source row lands in the warp.
        float4 A[4];
        #pragma unroll
        for (int k = 0; k < 4; k++) A[k] = src[(v0 + lane + 32 * k) & 127];

        float4* o = out4 + ((size_t)row << 7) + lane;
        o[ 0] = realign<0>(A, off, lane);
        o[32] = realign<1>(A, off, lane);
        o[64] = realign<2>(A, off, lane);
        o[96] = realign<3>(A, off, lane);
    }
}

// Scalar tail (defensive; these shapes divide into whole rows).
__global__ void random_roll_tail(const float* __restrict__ x,
                                 const int*   __restrict__ shifts,
                                 float*       __restrict__ out,
                                 int start, int total)
{
    int i = start + blockIdx.x * blockDim.x + threadIdx.x;
    if (i >= total) return;
    int w   = i & WMASK;
    int row = i >> 9;
    int h   = row & HMASK;
    int bc  = row >> 9;
    int b   = bc / 3;
    int sh = shifts[2 * b];
    int sw = shifts[2 * b + 1];
    out[i] = x[(((size_t)((bc << 9) | ((h - sh) & HMASK))) << 9) + ((w - sw) & WMASK)];
}

extern "C" void kernel_launch(void* const* d_in, const int* in_sizes, int n_in,
                              void* d_out, int out_size)
{
    const float4* x4     = (const float4*)d_in[0];
    const int*    shifts = (const int*)d_in[1];
    float4*       out4   = (float4*)d_out;

    int n_rows = out_size >> 9;                      // whole 512-float rows
    if (n_rows > 0) {
        int blocks = NSM * BLK_PER_SM;               // persistent: one wave
        int max_blocks = (n_rows + (TPB / 32) - 1) / (TPB / 32);
        if (blocks > max_blocks) blocks = max_blocks;
        random_roll_rows<<<blocks, TPB>>>(x4, shifts, out4, n_rows);
    }
    int tail_start = n_rows << 9;
    int tail = out_size - tail_start;
    if (tail > 0) {
        random_roll_tail<<<(tail + 255) / 256, 256>>>((const float*)d_in[0], shifts,
                                                      (float*)d_out, tail_start, out_size);
    }
}

// round 14
// speedup vs baseline: 1.1226x; 1.1226x over previous
#include <cuda_runtime.h>
#include <cstdint>

// RandomRoll: out[b,c,h,w] = x[b,c,(h - sh) & 511, (w - sw) & 511]
// x: [64, 3, 512, 512] fp32; shifts: [64, 2] int32.
// R11: flat launch, one warp per (h-even, h-odd) row PAIR. The pair shares
// (b,c) -> same (sh,sw) -> same off/v0, and the two SOURCE rows are adjacent
// ((src_h0+1)&511): 8 front-batched aligned LDG.128 cover 4KB contiguous.
// Circular realign closes in-warp via shuffle (lane 0 contributes A[k+1]).

static constexpr int HMASK = 511;
static constexpr int WMASK = 511;
static constexpr int TPB   = 256;
static constexpr unsigned FULL = 0xffffffffu;

// Realign output vec (lane + 32K) from in-register source row A[0..3].
// off warp-uniform (0..3). Neighbor of A[K]@lane is A[K]@lane+1; lane 31's
// neighbor is A[(K+1)&3]@lane0, contributed by lane 0 into the shuffle.
template<int K>
__device__ __forceinline__ float4 realign(const float4 A[4], int off, int lane)
{
    float4 a = A[K];
    if (off == 0) return a;
    const float4 an = A[(K + 1) & 3];
    int src = (lane + 1) & 31;
    float4 B;
    B.x = __shfl_sync(FULL, (lane == 0) ? an.x : a.x, src);
    B.y = __shfl_sync(FULL, (lane == 0) ? an.y : a.y, src);
    B.z = __shfl_sync(FULL, (lane == 0) ? an.z : a.z, src);
    B.w = __shfl_sync(FULL, (lane == 0) ? an.w : a.w, src);
    if (off == 1) return make_float4(a.y, a.z, a.w, B.x);
    if (off == 2) return make_float4(a.z, a.w, B.x, B.y);
    return make_float4(a.w, B.x, B.y, B.z);
}

__global__ void __launch_bounds__(TPB)
random_roll_pairs(const float4* __restrict__ x4,
                  const int*    __restrict__ shifts,
                  float4*       __restrict__ out4,
                  int n_pairs)   // pairs of rows; row = (b*3+c)*512 + h
{
    int lane = threadIdx.x & 31;
    int pair = blockIdx.x * (TPB / 32) + (threadIdx.x >> 5);
    if (pair >= n_pairs) return;

    int row0 = pair << 1;            // h even; row1 = row0 + 1 shares bc
    int h0   = row0 & HMASK;
    int bc   = row0 >> 9;
    int b    = bc / 3;

    int sh = __ldg(&shifts[2 * b]);
    int sw = __ldg(&shifts[2 * b + 1]);

    int src_h0 = (h0 - sh) & HMASK;
    int src_h1 = (src_h0 + 1) & HMASK;          // row1's source row (h0+1-sh)
    const float4* src0 = x4 + ((size_t)((bc << 9) | src_h0) << 7);
    const float4* src1 = x4 + ((size_t)((bc << 9) | src_h1) << 7);

    int s0  = (-sw) & WMASK;         // first source float of each rolled row
    int off = s0 & 3;                // shared by both rows (same sw)
    int v0  = s0 >> 2;

    // 8 aligned LDG.128 back-to-back; 4KB of (mostly) contiguous source.
    float4 A0[4], A1[4];
    #pragma unroll
    for (int k = 0; k < 4; k++) A0[k] = src0[(v0 + lane + 32 * k) & 127];
    #pragma unroll
    for (int k = 0; k < 4; k++) A1[k] = src1[(v0 + lane + 32 * k) & 127];

    float4* o0 = out4 + ((size_t)row0 << 7) + lane;   // row1 output = o0 + 128
    o0[  0] = realign<0>(A0, off, lane);
    o0[ 32] = realign<1>(A0, off, lane);
    o0[ 64] = realign<2>(A0, off, lane);
    o0[ 96] = realign<3>(A0, off, lane);
    o0[128] = realign<0>(A1, off, lane);
    o0[160] = realign<1>(A1, off, lane);
    o0[192] = realign<2>(A1, off, lane);
    o0[224] = realign<3>(A1, off, lane);
}

// Scalar tail (defensive; these shapes divide into whole row pairs).
__global__ void random_roll_tail(const float* __restrict__ x,
                                 const int*   __restrict__ shifts,
                                 float*       __restrict__ out,
                                 int start, int total)
{
    int i = start + blockIdx.x * blockDim.x + threadIdx.x;
    if (i >= total) return;
    int w   = i & WMASK;
    int row = i >> 9;
    int h   = row & HMASK;
    int bc  = row >> 9;
    int b   = bc / 3;
    int sh = shifts[2 * b];
    int sw = shifts[2 * b + 1];
    out[i] = x[(((size_t)((bc << 9) | ((h - sh) & HMASK))) << 9) + ((w - sw) & WMASK)];
}

extern "C" void kernel_launch(void* const* d_in, const int* in_sizes, int n_in,
                              void* d_out, int out_size)
{
    const float4* x4     = (const float4*)d_in[0];
    const int*    shifts = (const int*)d_in[1];
    float4*       out4   = (float4*)d_out;

    int n_rows  = out_size >> 9;                 // whole 512-float rows
    int n_pairs = n_rows >> 1;                   // H=512 even -> rows pair up
    if (n_pairs > 0) {
        int wpb    = TPB / 32;                   // 8 pairs per block
        int blocks = (n_pairs + wpb - 1) / wpb;
        random_roll_pairs<<<blocks, TPB>>>(x4, shifts, out4, n_pairs);
    }
    int tail_start = (n_pairs << 1) << 9;
    int tail = out_size - tail_start;
    if (tail > 0) {
        random_roll_tail<<<(tail + 255) / 256, 256>>>((const float*)d_in[0], shifts,
                                                      (float*)d_out, tail_start, out_size);
    }
}

// round 16
// speedup vs baseline: 1.1283x; 1.0050x over previous
#include <cuda_runtime.h>
#include <cstdint>

// RandomRoll: out[b,c,h,w] = x[b,c,(h - sh) & 511, (w - sw) & 511]
// x: [64, 3, 512, 512] fp32; shifts: [64, 2] int32.
// R15: R11 h-pair structure + ld.global.nc.L2::256B read hints.
// One warp per (h-even, h-odd) row pair: shared (sh,sw) -> shared off/v0,
// adjacent source rows -> 8 front-batched aligned LDG.128 over ~4KB contiguous.
// Circular realign closes in-warp via shuffle (lane 0 contributes A[k+1]).

static constexpr int HMASK = 511;
static constexpr int WMASK = 511;
static constexpr int TPB   = 256;
static constexpr unsigned FULL = 0xffffffffu;

__device__ __forceinline__ float4 ldg128_nc(const float4* p)
{
    float4 v;
    asm volatile("ld.global.nc.L2::256B.v4.f32 {%0,%1,%2,%3}, [%4];"
                 : "=f"(v.x), "=f"(v.y), "=f"(v.z), "=f"(v.w) : "l"(p));
    return v;
}

// Realign output vec (lane + 32K) from in-register source row A[0..3].
// off warp-uniform (0..3). Neighbor of A[K]@lane is A[K]@lane+1; lane 31's
// neighbor is A[(K+1)&3]@lane0, contributed by lane 0 into the shuffle.
template<int K>
__device__ __forceinline__ float4 realign(const float4 A[4], int off, int lane)
{
    float4 a = A[K];
    if (off == 0) return a;
    const float4 an = A[(K + 1) & 3];
    int src = (lane + 1) & 31;
    float4 B;
    B.x = __shfl_sync(FULL, (lane == 0) ? an.x : a.x, src);
    B.y = __shfl_sync(FULL, (lane == 0) ? an.y : a.y, src);
    B.z = __shfl_sync(FULL, (lane == 0) ? an.z : a.z, src);
    B.w = __shfl_sync(FULL, (lane == 0) ? an.w : a.w, src);
    if (off == 1) return make_float4(a.y, a.z, a.w, B.x);
    if (off == 2) return make_float4(a.z, a.w, B.x, B.y);
    return make_float4(a.w, B.x, B.y, B.z);
}

__global__ void __launch_bounds__(TPB)
random_roll_pairs(const float4* __restrict__ x4,
                  const int*    __restrict__ shifts,
                  float4*       __restrict__ out4,
                  int n_pairs)   // pairs of rows; row = (b*3+c)*512 + h
{
    int lane = threadIdx.x & 31;
    int pair = blockIdx.x * (TPB / 32) + (threadIdx.x >> 5);
    if (pair >= n_pairs) return;

    int row0 = pair << 1;            // h even; row1 = row0 + 1 shares bc
    int h0   = row0 & HMASK;
    int bc   = row0 >> 9;
    int b    = bc / 3;

    int sh = __ldg(&shifts[2 * b]);
    int sw = __ldg(&shifts[2 * b + 1]);

    int src_h0 = (h0 - sh) & HMASK;
    int src_h1 = (src_h0 + 1) & HMASK;          // row1's source row (h0+1-sh)
    const float4* src0 = x4 + ((size_t)((bc << 9) | src_h0) << 7);
    const float4* src1 = x4 + ((size_t)((bc << 9) | src_h1) << 7);

    int s0  = (-sw) & WMASK;         // first source float of each rolled row
    int off = s0 & 3;                // shared by both rows (same sw)
    int v0  = s0 >> 2;

    // 8 aligned LDG.128 back-to-back; ~4KB of contiguous source, L2::256B hint.
    float4 A0[4], A1[4];
    #pragma unroll
    for (int k = 0; k < 4; k++) A0[k] = ldg128_nc(src0 + ((v0 + lane + 32 * k) & 127));
    #pragma unroll
    for (int k = 0; k < 4; k++) A1[k] = ldg128_nc(src1 + ((v0 + lane + 32 * k) & 127));

    float4* o0 = out4 + ((size_t)row0 << 7) + lane;   // row1 output = o0 + 128
    o0[  0] = realign<0>(A0, off, lane);
    o0[ 32] = realign<1>(A0, off, lane);
    o0[ 64] = realign<2>(A0, off, lane);
    o0[ 96] = realign<3>(A0, off, lane);
    o0[128] = realign<0>(A1, off, lane);
    o0[160] = realign<1>(A1, off, lane);
    o0[192] = realign<2>(A1, off, lane);
    o0[224] = realign<3>(A1, off, lane);
}

// Scalar tail (defensive; these shapes divide into whole row pairs).
__global__ void random_roll_tail(const float* __restrict__ x,
                                 const int*   __restrict__ shifts,
                                 float*       __restrict__ out,
                                 int start, int total)
{
    int i = start + blockIdx.x * blockDim.x + threadIdx.x;
    if (i >= total) return;
    int w   = i & WMASK;
    int row = i >> 9;
    int h   = row & HMASK;
    int bc  = row >> 9;
    int b   = bc / 3;
    int sh = shifts[2 * b];
    int sw = shifts[2 * b + 1];
    out[i] = x[(((size_t)((bc << 9) | ((h - sh) & HMASK))) << 9) + ((w - sw) & WMASK)];
}

extern "C" void kernel_launch(void* const* d_in, const int* in_sizes, int n_in,
                              void* d_out, int out_size)
{
    const float4* x4     = (const float4*)d_in[0];
    const int*    shifts = (const int*)d_in[1];
    float4*       out4   = (float4*)d_out;

    int n_rows  = out_size >> 9;                 // whole 512-float rows
    int n_pairs = n_rows >> 1;                   // H=512 even -> rows pair up
    if (n_pairs > 0) {
        int wpb    = TPB / 32;                   // 8 pairs per block
        int blocks = (n_pairs + wpb - 1) / wpb;
        random_roll_pairs<<<blocks, TPB>>>(x4, shifts, out4, n_pairs);
    }
    int tail_start = (n_pairs << 1) << 9;
    int tail = out_size - tail_start;
    if (tail > 0) {
        random_roll_tail<<<(tail + 255) / 256, 256>>>((const float*)d_in[0], shifts,
                                                      (float*)d_out, tail_start, out_size);
    }
}